// round 4
// baseline (speedup 1.0000x reference)
#include <cuda_runtime.h>
#include <math.h>

#define Nn 4096
#define Dd 384
#define Ee 131072
#define Hh 8
#define DHh 48
#define Ll 3

// ---------------- scratch (static device globals; no runtime alloc) ----------
__device__ float g_h[Nn * Dd];
__device__ float g_agg[Nn * Dd];
__device__ float g_hnew[Nn * Dd];
__device__ float g_qkv[Nn * 3 * Dd];
__device__ float g_o[Nn * Dd];
__device__ int   g_deg[Nn];
__device__ float g_degf[Nn];
__device__ int   g_rowptr[Nn + 1];
__device__ int   g_fillpos[Nn];
__device__ int   g_colidx[Ee];

// ---------------- CSR build --------------------------------------------------
__global__ void k_zero_deg() {
    int i = blockIdx.x * blockDim.x + threadIdx.x;
    if (i < Nn) g_deg[i] = 0;
}

__global__ void k_hist(const int* __restrict__ ei) {
    int e = blockIdx.x * blockDim.x + threadIdx.x;
    if (e < Ee) atomicAdd(&g_deg[ei[e]], 1);
}

__global__ void k_scan() {
    __shared__ int s[1024];
    int tid = threadIdx.x;
    int b = tid * 4;
    int v0 = g_deg[b], v1 = g_deg[b + 1], v2 = g_deg[b + 2], v3 = g_deg[b + 3];
    int p1 = v0 + v1, p2 = p1 + v2, p3 = p2 + v3;
    s[tid] = p3;
    __syncthreads();
    for (int off = 1; off < 1024; off <<= 1) {
        int t = (tid >= off) ? s[tid - off] : 0;
        __syncthreads();
        if (tid >= off) s[tid] += t;
        __syncthreads();
    }
    int prev = tid ? s[tid - 1] : 0;
    int e0 = prev, e1 = prev + v0, e2 = prev + p1, e3 = prev + p2;
    g_rowptr[b]     = e0; g_rowptr[b + 1] = e1;
    g_rowptr[b + 2] = e2; g_rowptr[b + 3] = e3;
    g_fillpos[b]     = e0; g_fillpos[b + 1] = e1;
    g_fillpos[b + 2] = e2; g_fillpos[b + 3] = e3;
    g_degf[b]     = (float)v0; g_degf[b + 1] = (float)v1;
    g_degf[b + 2] = (float)v2; g_degf[b + 3] = (float)v3;
    if (tid == 1023) g_rowptr[Nn] = s[1023];
}

__global__ void k_fill(const int* __restrict__ ei) {
    int e = blockIdx.x * blockDim.x + threadIdx.x;
    if (e < Ee) {
        int dst = ei[e];
        int src = ei[Ee + e];
        int pos = atomicAdd(&g_fillpos[dst], 1);
        g_colidx[pos] = src;
    }
}

__global__ void k_copy(const float* __restrict__ emb) {
    int i = blockIdx.x * blockDim.x + threadIdx.x;
    if (i < Nn * Dd / 4)
        ((float4*)g_h)[i] = ((const float4*)emb)[i];
}

// ---------------- neighbor aggregation (warp per node, deterministic) --------
__global__ __launch_bounds__(256) void k_gather() {
    int warp = (blockIdx.x * blockDim.x + threadIdx.x) >> 5;
    int lane = threadIdx.x & 31;
    if (warp >= Nn) return;
    int pbeg = g_rowptr[warp], pend = g_rowptr[warp + 1];
    float4 a0 = {0, 0, 0, 0}, a1 = a0, a2 = a0;
    for (int p = pbeg; p < pend; p++) {
        int src = g_colidx[p];
        const float4* r = (const float4*)(g_h + src * Dd);
        float4 x;
        x = r[lane];      a0.x += x.x; a0.y += x.y; a0.z += x.z; a0.w += x.w;
        x = r[lane + 32]; a1.x += x.x; a1.y += x.y; a1.z += x.z; a1.w += x.w;
        x = r[lane + 64]; a2.x += x.x; a2.y += x.y; a2.z += x.z; a2.w += x.w;
    }
    float4* w = (float4*)(g_agg + warp * Dd);
    w[lane] = a0; w[lane + 32] = a1; w[lane + 64] = a2;
}

// ---------------- GEMM: C[m][n] = sum_k A[m][k]*B[n][k] + epilogue -----------
// MODE 0: A=g_agg  -> C=g_hnew, bias scaled by per-row degree        (conv)
// MODE 1: A=g_hnew -> C=g_qkv,  plain bias, Nout=3D                  (qkv)
// MODE 2: A=g_o    -> C=g_h,    bias + residual g_h, relu, in-place  (attn out)
template <int MODE>
__global__ __launch_bounds__(256) void k_gemm(const float* __restrict__ B,
                                              const float* __restrict__ bias) {
    const float* A;
    float* C;
    int Nout;
    if (MODE == 0)      { A = g_agg;  C = g_hnew; Nout = Dd; }
    else if (MODE == 1) { A = g_hnew; C = g_qkv;  Nout = 3 * Dd; }
    else                { A = g_o;    C = g_h;    Nout = Dd; }

    __shared__ __align__(16) float As[32 * 68];
    __shared__ __align__(16) float Bs[32 * 68];
    int tid = threadIdx.x;
    int tx = tid & 15, ty = tid >> 4;
    int row0 = blockIdx.y * 64, col0 = blockIdx.x * 64;

    float acc[4][4];
#pragma unroll
    for (int i = 0; i < 4; i++)
#pragma unroll
        for (int j = 0; j < 4; j++) acc[i][j] = 0.f;

    for (int k0 = 0; k0 < Dd; k0 += 32) {
#pragma unroll
        for (int i = tid; i < 64 * 32; i += 256) {
            int m = i >> 5, k = i & 31;
            As[k * 68 + m] = A[(row0 + m) * Dd + k0 + k];
        }
#pragma unroll
        for (int i = tid; i < 64 * 32; i += 256) {
            int n = i >> 5, k = i & 31;
            Bs[k * 68 + n] = B[(col0 + n) * Dd + k0 + k];
        }
        __syncthreads();
#pragma unroll 8
        for (int kk = 0; kk < 32; kk++) {
            float4 a4 = *(const float4*)&As[kk * 68 + ty * 4];
            float4 b4 = *(const float4*)&Bs[kk * 68 + tx * 4];
            float av[4] = {a4.x, a4.y, a4.z, a4.w};
            float bv[4] = {b4.x, b4.y, b4.z, b4.w};
#pragma unroll
            for (int i = 0; i < 4; i++)
#pragma unroll
                for (int j = 0; j < 4; j++) acc[i][j] += av[i] * bv[j];
        }
        __syncthreads();
    }

#pragma unroll
    for (int i = 0; i < 4; i++) {
        int m = row0 + ty * 4 + i;
        float rmul = (MODE == 0) ? g_degf[m] : 1.0f;
#pragma unroll
        for (int j = 0; j < 4; j++) {
            int n = col0 + tx * 4 + j;
            float v = acc[i][j] + bias[n] * rmul;
            if (MODE == 2) {
                v += g_h[m * Dd + n];
                v = fmaxf(v, 0.f);
            }
            C[m * Nout + n] = v;
        }
    }
}

// ---------------- flash attention: per (head, 64-query tile) -----------------
__global__ __launch_bounds__(256) void k_flash() {
    extern __shared__ __align__(16) float sm[];
    float* Qs = sm;            // [48][64]
    float* Ks = sm + 3072;     // [48][64]
    float* Vs = sm + 6144;     // [64][48]
    float* Ps = sm + 9216;     // [64][68]
    int head = blockIdx.y;
    int q0 = blockIdx.x * 64;
    int tid = threadIdx.x, tx = tid & 15, ty = tid >> 4;
    const float scale = 0.14433756729740643f;  // 1/sqrt(48)

    for (int i = tid; i < 3072; i += 256) {
        int m = i / 48, d = i - m * 48;
        Qs[d * 64 + m] = g_qkv[(q0 + m) * 1152 + head * 48 + d] * scale;
    }

    float mr[4], lr[4], O[4][3];
#pragma unroll
    for (int i = 0; i < 4; i++) {
        mr[i] = -1e30f; lr[i] = 0.f;
        O[i][0] = O[i][1] = O[i][2] = 0.f;
    }
    __syncthreads();

    for (int k0 = 0; k0 < Nn; k0 += 64) {
        for (int i = tid; i < 3072; i += 256) {
            int n = i / 48, d = i - n * 48;
            Ks[d * 64 + n] = g_qkv[(k0 + n) * 1152 + 384 + head * 48 + d];
        }
        for (int i = tid; i < 3072; i += 256) {
            int n = i / 48, d = i - n * 48;
            Vs[n * 48 + d] = g_qkv[(k0 + n) * 1152 + 768 + head * 48 + d];
        }
        __syncthreads();

        // S = Q K^T (scale folded into Q)
        float s[4][4];
#pragma unroll
        for (int i = 0; i < 4; i++)
#pragma unroll
            for (int j = 0; j < 4; j++) s[i][j] = 0.f;
#pragma unroll 8
        for (int kk = 0; kk < 48; kk++) {
            float4 q4 = *(const float4*)&Qs[kk * 64 + ty * 4];
            float4 c4 = *(const float4*)&Ks[kk * 64 + tx * 4];
            float qa[4] = {q4.x, q4.y, q4.z, q4.w};
            float kb[4] = {c4.x, c4.y, c4.z, c4.w};
#pragma unroll
            for (int i = 0; i < 4; i++)
#pragma unroll
                for (int j = 0; j < 4; j++) s[i][j] += qa[i] * kb[j];
        }

        // online softmax (row stats across the 16-thread row group)
#pragma unroll
        for (int i = 0; i < 4; i++) {
            float vmax = fmaxf(fmaxf(s[i][0], s[i][1]), fmaxf(s[i][2], s[i][3]));
#pragma unroll
            for (int off = 8; off; off >>= 1)
                vmax = fmaxf(vmax, __shfl_xor_sync(0xffffffffu, vmax, off));
            float nm = fmaxf(mr[i], vmax);
            float sum = 0.f;
#pragma unroll
            for (int j = 0; j < 4; j++) {
                s[i][j] = __expf(s[i][j] - nm);
                sum += s[i][j];
            }
#pragma unroll
            for (int off = 8; off; off >>= 1)
                sum += __shfl_xor_sync(0xffffffffu, sum, off);
            float alpha = __expf(mr[i] - nm);
            lr[i] = lr[i] * alpha + sum;
            mr[i] = nm;
            O[i][0] *= alpha; O[i][1] *= alpha; O[i][2] *= alpha;
        }

#pragma unroll
        for (int i = 0; i < 4; i++)
#pragma unroll
            for (int j = 0; j < 4; j++)
                Ps[(ty * 4 + i) * 68 + tx * 4 + j] = s[i][j];
        __syncthreads();

        // O += P V
        int c0 = tx * 3;
#pragma unroll 4
        for (int j = 0; j < 64; j++) {
            float v0 = Vs[j * 48 + c0];
            float v1 = Vs[j * 48 + c0 + 1];
            float v2 = Vs[j * 48 + c0 + 2];
#pragma unroll
            for (int i = 0; i < 4; i++) {
                float p = Ps[(ty * 4 + i) * 68 + j];
                O[i][0] += p * v0; O[i][1] += p * v1; O[i][2] += p * v2;
            }
        }
        __syncthreads();
    }

#pragma unroll
    for (int i = 0; i < 4; i++) {
        float inv = 1.f / lr[i];
        int n = q0 + ty * 4 + i;
        g_o[n * 384 + head * 48 + tx * 3 + 0] = O[i][0] * inv;
        g_o[n * 384 + head * 48 + tx * 3 + 1] = O[i][1] * inv;
        g_o[n * 384 + head * 48 + tx * 3 + 2] = O[i][2] * inv;
    }
}

// ---------------- output projection + sigmoid --------------------------------
__global__ __launch_bounds__(256) void k_out(const float* __restrict__ Wout,
                                             const float* __restrict__ bout,
                                             float* __restrict__ out) {
    int warp = (blockIdx.x * blockDim.x + threadIdx.x) >> 5;
    int lane = threadIdx.x & 31;
    if (warp >= Nn) return;
    const float4* hr = (const float4*)(g_h + warp * Dd);
    const float4* wr = (const float4*)Wout;
    float s = 0.f;
#pragma unroll
    for (int q = 0; q < 3; q++) {
        float4 a = hr[lane + 32 * q];
        float4 b = wr[lane + 32 * q];
        s += a.x * b.x + a.y * b.y + a.z * b.z + a.w * b.w;
    }
#pragma unroll
    for (int off = 16; off; off >>= 1)
        s += __shfl_xor_sync(0xffffffffu, s, off);
    if (lane == 0) out[warp] = 1.f / (1.f + __expf(-(s + bout[0])));
}

// ---------------- launch ------------------------------------------------------
extern "C" void kernel_launch(void* const* d_in, const int* in_sizes, int n_in,
                              void* d_out, int out_size) {
    const float* emb  = (const float*)d_in[0];
    const int*   ei   = (const int*)d_in[1];
    const float* Wc   = (const float*)d_in[2];
    const float* bc   = (const float*)d_in[3];
    const float* Win  = (const float*)d_in[4];
    const float* bin  = (const float*)d_in[5];
    const float* Wao  = (const float*)d_in[6];
    const float* bao  = (const float*)d_in[7];
    const float* Wout = (const float*)d_in[8];
    const float* bout = (const float*)d_in[9];
    float* out = (float*)d_out;

    cudaFuncSetAttribute(k_flash, cudaFuncAttributeMaxDynamicSharedMemorySize,
                         13568 * 4);

    // CSR build (reused across all 3 layers)
    k_zero_deg<<<Nn / 256, 256>>>();
    k_hist<<<Ee / 256, 256>>>(ei);
    k_scan<<<1, 1024>>>();
    k_fill<<<Ee / 256, 256>>>(ei);
    k_copy<<<(Nn * Dd / 4) / 256, 256>>>(emb);

    for (int l = 0; l < Ll; l++) {
        k_gather<<<Nn / 8, 256>>>();
        k_gemm<0><<<dim3(Dd / 64, Nn / 64), 256>>>(Wc + l * Dd * Dd, bc + l * Dd);
        k_gemm<1><<<dim3(3 * Dd / 64, Nn / 64), 256>>>(Win, bin);
        k_flash<<<dim3(Nn / 64, Hh), 256, 13568 * 4>>>();
        k_gemm<2><<<dim3(Dd / 64, Nn / 64), 256>>>(Wao, bao);
    }
    k_out<<<Nn / 8, 256>>>(Wout, bout, out);
}